// round 2
// baseline (speedup 1.0000x reference)
#include <cuda_runtime.h>

// RoPE via sparse exploitation of the block-diagonal rotation matrices.
// Inputs (metadata order): x fp32 [2,2048,128], token_positions int32 [2,2048]
// (JAX x64 disabled -> "int64" is really int32), R fp32 [2048,128,128].
// Output fp32 [2,2048,128].
//
// R[p] is block-diagonal with 2x2 rotations; R[p,2k,2k] = c, R[p,2k,2k+1] = -s
// are adjacent -> a single aligned float2 gather yields the exact coefficients
// used by the reference einsum (2 nonzeros per output row), so results match
// to fp32 rounding.

__global__ void __launch_bounds__(256)
rope_gather_kernel(const float* __restrict__ x,
                   const int* __restrict__ token_positions,
                   const float* __restrict__ R,
                   float* __restrict__ out,
                   int total_pairs) {
    int idx = blockIdx.x * blockDim.x + threadIdx.x;
    if (idx >= total_pairs) return;

    int token = idx >> 6;        // 64 pairs per token (d_k = 128)
    int k2    = (idx & 63) << 1; // even dim index 2k

    unsigned p = (unsigned)__ldg(&token_positions[token]);
    if (p >= 2048u) p = 0u;      // guard: never fault on unexpected data

    // (c, -s) adjacent in row 2k of R[p]: offset = p*128*128 + 2k*128 + 2k
    const float2 cms = *reinterpret_cast<const float2*>(
        R + (long long)p * 16384LL + (long long)k2 * 129LL);
    const float c  = cms.x;
    const float ms = cms.y;   // ms = -s

    const float2 xv = *reinterpret_cast<const float2*>(x + (long long)token * 128 + k2);

    float2 o;
    o.x = c * xv.x + ms * xv.y;   // c*x0 - s*x1
    o.y = c * xv.y - ms * xv.x;   // s*x0 + c*x1

    *reinterpret_cast<float2*>(out + (long long)token * 128 + k2) = o;
}

extern "C" void kernel_launch(void* const* d_in, const int* in_sizes, int n_in,
                              void* d_out, int out_size) {
    const float* x   = (const float*)d_in[0];
    const int*   pos = (const int*)d_in[1];
    const float* R   = (const float*)d_in[2];
    float*       out = (float*)d_out;

    const int total_pairs = out_size / 2;  // one thread per (token, 2k) pair
    const int threads = 256;
    const int blocks  = (total_pairs + threads - 1) / threads;
    rope_gather_kernel<<<blocks, threads>>>(x, pos, R, out, total_pairs);
}

// round 3
// speedup vs baseline: 1.0337x; 1.0337x over previous
#include <cuda_runtime.h>

// RoPE exploiting block-diagonal structure of R. LSU-issue-bound kernel:
// minimize memory-instruction count, not bytes.
//
// Inputs: x fp32 [2,2048,128], token_positions int32 [2,2048],
//         R fp32 [2048,128,128]. Output fp32 [2,2048,128].
//
// Each thread handles 4 rotation pairs (8 floats) of one token:
//   1x LDG.32 (pos) + 4x LDG.64 (adjacent (c,-s) in R rows, 516B-strided,
//   not coalescable) + 2x LDG.128 (x) + 2x STG.128 (out) = 9 mem ops / 4 pairs.

__global__ void __launch_bounds__(128)
rope_gather4_kernel(const float* __restrict__ x,
                    const int* __restrict__ token_positions,
                    const float* __restrict__ R,
                    float* __restrict__ out,
                    int n_threads) {
    int idx = blockIdx.x * blockDim.x + threadIdx.x;
    if (idx >= n_threads) return;

    int token = idx >> 4;          // 16 threads per token (64 pairs / 4)
    int k     = (idx & 15) << 2;   // base pair index: pairs k..k+3

    unsigned p = (unsigned)__ldg(&token_positions[token]);
    if (p >= 2048u) p = 0u;        // never fault on unexpected data

    const float* Rp = R + (size_t)p * 16384;

    // (c, -s) at R[p, 2m, 2m..2m+1] -> float offset 2m*128 + 2m = m*258.
    // Four independent gathers (front-batched for MLP).
    const float2 c0 = *reinterpret_cast<const float2*>(Rp + (size_t)(k + 0) * 258);
    const float2 c1 = *reinterpret_cast<const float2*>(Rp + (size_t)(k + 1) * 258);
    const float2 c2 = *reinterpret_cast<const float2*>(Rp + (size_t)(k + 2) * 258);
    const float2 c3 = *reinterpret_cast<const float2*>(Rp + (size_t)(k + 3) * 258);

    const float* xt = x + (size_t)token * 128 + (size_t)k * 2;
    const float4 xa = *reinterpret_cast<const float4*>(xt);      // pairs k, k+1
    const float4 xb = *reinterpret_cast<const float4*>(xt + 4);  // pairs k+2, k+3

    // o_even = c*x_even - s*x_odd ; o_odd = s*x_even + c*x_odd  (c?.y == -s)
    float4 oa, ob;
    oa.x = c0.x * xa.x + c0.y * xa.y;
    oa.y = c0.x * xa.y - c0.y * xa.x;
    oa.z = c1.x * xa.z + c1.y * xa.w;
    oa.w = c1.x * xa.w - c1.y * xa.z;
    ob.x = c2.x * xb.x + c2.y * xb.y;
    ob.y = c2.x * xb.y - c2.y * xb.x;
    ob.z = c3.x * xb.z + c3.y * xb.w;
    ob.w = c3.x * xb.w - c3.y * xb.z;

    float* ot = out + (size_t)token * 128 + (size_t)k * 2;
    *reinterpret_cast<float4*>(ot)     = oa;
    *reinterpret_cast<float4*>(ot + 4) = ob;
}

extern "C" void kernel_launch(void* const* d_in, const int* in_sizes, int n_in,
                              void* d_out, int out_size) {
    const float* x   = (const float*)d_in[0];
    const int*   pos = (const int*)d_in[1];
    const float* R   = (const float*)d_in[2];
    float*       out = (float*)d_out;

    const int n_threads = out_size / 8;   // 4 pairs (8 floats) per thread
    const int threads = 128;
    const int blocks  = (n_threads + threads - 1) / threads;
    rope_gather4_kernel<<<blocks, threads>>>(x, pos, R, out, n_threads);
}